// round 1
// baseline (speedup 1.0000x reference)
#include <cuda_runtime.h>
#include <cstdint>

// Problem dims (fixed for this instance)
#define B_  4
#define N_  4096      // 64*64
#define T_  3
#define D_  256
#define HH  8
#define PP  9
#define DH  32
#define GRID_W 64
#define M_  (B_*N_)   // 16384 rows
#define NOFF 144      // HH*PP*2
#define NATT 72       // HH*PP
#define NOA  216

// ---------------- device scratch (static; no allocation allowed) ----------
__device__ float g_xsum[(size_t)M_*D_];     // sum over T of x
__device__ float g_query[(size_t)M_*D_];    // x[:, :, 1, :]
__device__ float g_offattn[(size_t)M_*NOA]; // [bn][0:144 offsets | 144:216 attn logits]
__device__ float g_vimg[(size_t)M_*D_];     // [(b*8+h)][n=y*64+x][c]  (32 imgs of 64x64x32)
__device__ float g_headout[(size_t)M_*D_];  // [bn][h*32+c]

// ---------------- prep: xsum + query --------------------------------------
__global__ void __launch_bounds__(256) prep_kernel(const float* __restrict__ x) {
    int idx = blockIdx.x * 256 + threadIdx.x;      // over M_*D_
    int r = idx >> 8;          // row (b*N+n)
    int d = idx & 255;
    const float* base = x + ((size_t)r * 3) * 256 + d;
    float x0 = base[0];
    float x1 = base[256];
    float x2 = base[512];
    g_xsum[idx]  = x0 + x1 + x2;
    g_query[idx] = x1;
}

// ---------------- SGEMM: C(MxNb) = A(Mx256) * B(256xNb) + bscale*bias -----
// MODE 0: C[m*ldc + n]          (row-major with leading dim ldc)
// MODE 1: scatter to vimg layout (((b*8+h)*4096+n)*32+c), ldc ignored
template<int MODE>
__global__ void __launch_bounds__(256) sgemm_kernel(
        const float* __restrict__ A, const float* __restrict__ Bm,
        const float* __restrict__ bias, float bscale,
        float* __restrict__ C, int Nb, int ldc)
{
    __shared__ float As[16][64];
    __shared__ float Bs[16][64];
    const int tid = threadIdx.x;
    const int mtile = blockIdx.y * 64;
    const int ntile = blockIdx.x * 64;
    const int tx = tid & 15;
    const int ty = tid >> 4;
    const int K = 256;

    float acc[4][4];
#pragma unroll
    for (int i = 0; i < 4; i++)
#pragma unroll
        for (int j = 0; j < 4; j++) acc[i][j] = 0.f;

    for (int k0 = 0; k0 < K; k0 += 16) {
        // Load A tile 64x16 -> As[k][m]
#pragma unroll
        for (int i = 0; i < 4; i++) {
            int e = tid + i * 256;
            int row = e >> 4, kk = e & 15;
            As[kk][row] = A[(size_t)(mtile + row) * K + k0 + kk];
        }
        // Load B tile 16x64 -> Bs[k][n]
#pragma unroll
        for (int i = 0; i < 4; i++) {
            int e = tid + i * 256;
            int kk = e >> 6, col = e & 63;
            int gc = ntile + col;
            Bs[kk][col] = (gc < Nb) ? Bm[(size_t)(k0 + kk) * Nb + gc] : 0.f;
        }
        __syncthreads();
#pragma unroll
        for (int kk = 0; kk < 16; kk++) {
            float4 av = *(const float4*)&As[kk][ty * 4];
            float4 bv = *(const float4*)&Bs[kk][tx * 4];
            float ar[4] = {av.x, av.y, av.z, av.w};
            float br[4] = {bv.x, bv.y, bv.z, bv.w};
#pragma unroll
            for (int i = 0; i < 4; i++)
#pragma unroll
                for (int j = 0; j < 4; j++)
                    acc[i][j] = fmaf(ar[i], br[j], acc[i][j]);
        }
        __syncthreads();
    }

#pragma unroll
    for (int i = 0; i < 4; i++) {
        int m = mtile + ty * 4 + i;
#pragma unroll
        for (int j = 0; j < 4; j++) {
            int nn = ntile + tx * 4 + j;
            if (nn >= Nb) continue;
            float v = acc[i][j];
            if (bias) v = fmaf(bscale, bias[nn], v);
            if (MODE == 0) {
                C[(size_t)m * ldc + nn] = v;
            } else {
                int b = m >> 12, n = m & 4095;
                int h = nn >> 5, c = nn & 31;
                C[(((size_t)(b * 8 + h) * 4096 + n) << 5) + c] = v;
            }
        }
    }
}

// ---------------- sampling + softmax + attention-weighted sum -------------
// block = 256 threads = 8 warps; block per (b,n); warp = head; lane = channel
__global__ void __launch_bounds__(256) sample_kernel(float* __restrict__ headout) {
    const int bn = blockIdx.x;               // b*4096 + n
    const int h = threadIdx.x >> 5;
    const int lane = threadIdx.x & 31;
    const int b = bn >> 12;
    const int n = bn & 4095;

    const float* oa = g_offattn + (size_t)bn * NOA;

    // softmax over P=9 attn logits (lane-uniform, broadcast loads)
    float w[PP];
    float mx = -1e30f;
#pragma unroll
    for (int p = 0; p < PP; p++) {
        w[p] = oa[NOFF + h * PP + p];
        mx = fmaxf(mx, w[p]);
    }
    float s = 0.f;
#pragma unroll
    for (int p = 0; p < PP; p++) { w[p] = __expf(w[p] - mx); s += w[p]; }
    float inv = 1.f / s;
#pragma unroll
    for (int p = 0; p < PP; p++) w[p] *= inv;

    // reference grid location (normalized), n = row*64 + col; ref = (gw, gh)
    const float ref_xn = (float)(n & 63) * (2.0f / 63.0f) - 1.0f;
    const float ref_yn = (float)(n >> 6) * (2.0f / 63.0f) - 1.0f;

    const float* img = g_vimg + ((size_t)(b * 8 + h)) * (4096u * 32u);

    float acc = 0.f;
#pragma unroll
    for (int p = 0; p < PP; p++) {
        float ox = oa[h * 18 + p * 2 + 0];
        float oy = oa[h * 18 + p * 2 + 1];
        float gx = (ref_xn + ox + 1.0f) * 0.5f * 63.0f;
        float gy = (ref_yn + oy + 1.0f) * 0.5f * 63.0f;
        float x0f = floorf(gx), y0f = floorf(gy);
        int x0 = (int)x0f, y0 = (int)y0f;
        float wx1 = gx - x0f, wy1 = gy - y0f;
        float wx0 = 1.f - wx1, wy0 = 1.f - wy1;

        bool vx0 = (x0 >= 0) & (x0 < 64);
        bool vx1 = (x0 >= -1) & (x0 < 63);
        bool vy0 = (y0 >= 0) & (y0 < 64);
        bool vy1 = (y0 >= -1) & (y0 < 63);

        float v00 = (vx0 && vy0) ? img[((size_t)(y0 * 64 + x0) << 5) + lane] : 0.f;
        float v10 = (vx1 && vy0) ? img[((size_t)(y0 * 64 + x0 + 1) << 5) + lane] : 0.f;
        float v01 = (vx0 && vy1) ? img[((size_t)((y0 + 1) * 64 + x0) << 5) + lane] : 0.f;
        float v11 = (vx1 && vy1) ? img[((size_t)((y0 + 1) * 64 + x0 + 1) << 5) + lane] : 0.f;

        float bil = wx0 * wy0 * v00 + wx1 * wy0 * v10 + wx0 * wy1 * v01 + wx1 * wy1 * v11;
        acc = fmaf(w[p], bil, acc);
    }
    headout[(size_t)bn * D_ + h * DH + lane] = acc;
}

// ---------------- launch ---------------------------------------------------
extern "C" void kernel_launch(void* const* d_in, const int* in_sizes, int n_in,
                              void* d_out, int out_size) {
    const float* x      = (const float*)d_in[0];
    const float* W_off  = (const float*)d_in[1];
    const float* b_off  = (const float*)d_in[2];
    const float* W_attn = (const float*)d_in[3];
    const float* b_attn = (const float*)d_in[4];
    const float* W_v    = (const float*)d_in[5];
    const float* b_v    = (const float*)d_in[6];
    const float* W_o    = (const float*)d_in[7];
    const float* b_o    = (const float*)d_in[8];
    float* out = (float*)d_out;

    float *p_xsum, *p_query, *p_offattn, *p_vimg, *p_headout;
    cudaGetSymbolAddress((void**)&p_xsum,    g_xsum);
    cudaGetSymbolAddress((void**)&p_query,   g_query);
    cudaGetSymbolAddress((void**)&p_offattn, g_offattn);
    cudaGetSymbolAddress((void**)&p_vimg,    g_vimg);
    cudaGetSymbolAddress((void**)&p_headout, g_headout);

    // 1. prep: xsum + query
    prep_kernel<<<(M_ * D_) / 256, 256>>>(x);

    // 2. offsets: query @ W_off (Nb=144, ldc=216)
    sgemm_kernel<0><<<dim3(3, M_ / 64), 256>>>(p_query, W_off, b_off, 1.0f,
                                               p_offattn, NOFF, NOA);
    // 3. attn logits: query @ W_attn (Nb=72, write at column offset 144)
    sgemm_kernel<0><<<dim3(2, M_ / 64), 256>>>(p_query, W_attn, b_attn, 1.0f,
                                               p_offattn + NOFF, NATT, NOA);
    // 4. value images: xsum @ W_v + 3*b_v, scattered to per-(b,h) image layout
    sgemm_kernel<1><<<dim3(4, M_ / 64), 256>>>(p_xsum, W_v, b_v, 3.0f,
                                               p_vimg, D_, 0);
    // 5. softmax + bilinear sampling + attention reduce
    sample_kernel<<<M_, 256>>>(p_headout);

    // 6. output projection: headout @ W_o + b_o
    sgemm_kernel<0><<<dim3(4, M_ / 64), 256>>>(p_headout, W_o, b_o, 1.0f,
                                               out, D_, D_);
}

// round 2
// speedup vs baseline: 1.4872x; 1.4872x over previous
#include <cuda_runtime.h>
#include <cuda_fp16.h>
#include <cstdint>

#define B_  4
#define N_  4096      // 64*64
#define D_  256
#define HH  8
#define PP  9
#define DH  32
#define M_  (B_*N_)   // 16384
#define NOFF 144
#define NATT 72
#define NOA  216      // 144 + 72

// ---------------- device scratch (static) ----------------------------------
__device__ float  g_woa[256 * NOA];          // packed [W_off | W_attn]
__device__ float  g_boa[NOA];                // packed [b_off | b_attn]
__device__ float  g_offattn[(size_t)M_ * NOA];
__device__ __half g_vimg[(size_t)M_ * D_];   // [(b*8+h)][n=y*64+x][c] fp16
__device__ float  g_headout[(size_t)M_ * D_];

// ---------------- pack W_off/W_attn into one 256x216 matrix ----------------
__global__ void __launch_bounds__(256) pack_kernel(
        const float* __restrict__ Woff, const float* __restrict__ boff,
        const float* __restrict__ Watt, const float* __restrict__ batt) {
    int k = blockIdx.x;          // 0..255
    int c = threadIdx.x;         // 0..255
    if (c < NOA) {
        float v = (c < NOFF) ? Woff[k * NOFF + c] : Watt[k * NATT + (c - NOFF)];
        g_woa[k * NOA + c] = v;
        if (k == 0) g_boa[c] = (c < NOFF) ? boff[c] : batt[c - NOFF];
    }
}

// ---------------- GEMM: C(Mx Nb) = A(Mx256) * B(256xNb) + bscale*bias ------
// BM=128, BN=128, BK=16, 256 threads, 8x8 microtile.
// AMODE 0: A row-major with leading dim lda (lda=768 gives strided query read)
// AMODE 1: A row = sum of 3 temporal rows (x summed over T), lda=768
// CMODE 0: fp32 row-major ldc
// CMODE 1: fp16 scatter to vimg layout (((b*8+h)*4096+n)*32+c)
template<int AMODE, int CMODE>
__global__ void __launch_bounds__(256, 2) gemm_k(
        const float* __restrict__ A, int lda,
        const float* __restrict__ Bm, int Nb,
        const float* __restrict__ bias, float bscale,
        float* __restrict__ C, int ldc, __half* __restrict__ Ch)
{
    __shared__ float As[16][128];
    __shared__ float Bs[16][128];
    const int tid = threadIdx.x;
    const int mtile = blockIdx.y * 128;
    const int ntile = blockIdx.x * 128;
    const int tx = tid & 15;
    const int ty = tid >> 4;

    // loader indices
    const int ar = tid >> 1;            // A row within tile, 0..127
    const int ak = (tid & 1) * 8;       // A k offset: 0 or 8
    const int bk = tid >> 4;            // B k within tile, 0..15
    const int bn = (tid & 15) * 8;      // B col offset, 0..120

    float acc[8][8];
#pragma unroll
    for (int i = 0; i < 8; i++)
#pragma unroll
        for (int j = 0; j < 8; j++) acc[i][j] = 0.f;

    const float* Arow = A + (size_t)(mtile + ar) * lda;

    for (int k0 = 0; k0 < 256; k0 += 16) {
        // ---- load A tile (transpose into As[k][m]) ----
        float4 a0, a1;
        const float* Ap = Arow + k0 + ak;
        if (AMODE == 0) {
            a0 = *(const float4*)Ap;
            a1 = *(const float4*)(Ap + 4);
        } else {
            float4 t0 = *(const float4*)(Ap);
            float4 t1 = *(const float4*)(Ap + 256);
            float4 t2 = *(const float4*)(Ap + 512);
            a0 = make_float4(t0.x + t1.x + t2.x, t0.y + t1.y + t2.y,
                             t0.z + t1.z + t2.z, t0.w + t1.w + t2.w);
            float4 u0 = *(const float4*)(Ap + 4);
            float4 u1 = *(const float4*)(Ap + 260);
            float4 u2 = *(const float4*)(Ap + 516);
            a1 = make_float4(u0.x + u1.x + u2.x, u0.y + u1.y + u2.y,
                             u0.z + u1.z + u2.z, u0.w + u1.w + u2.w);
        }
        As[ak + 0][ar] = a0.x; As[ak + 1][ar] = a0.y;
        As[ak + 2][ar] = a0.z; As[ak + 3][ar] = a0.w;
        As[ak + 4][ar] = a1.x; As[ak + 5][ar] = a1.y;
        As[ak + 6][ar] = a1.z; As[ak + 7][ar] = a1.w;

        // ---- load B tile ----
        {
            const float* Bp = Bm + (size_t)(k0 + bk) * Nb + ntile + bn;
            int gc = ntile + bn;
            float4 b0 = (gc + 4 <= Nb) ? *(const float4*)Bp
                                       : make_float4(0.f, 0.f, 0.f, 0.f);
            float4 b1 = (gc + 8 <= Nb) ? *(const float4*)(Bp + 4)
                                       : make_float4(0.f, 0.f, 0.f, 0.f);
            *(float4*)&Bs[bk][bn]     = b0;
            *(float4*)&Bs[bk][bn + 4] = b1;
        }
        __syncthreads();

#pragma unroll
        for (int kk = 0; kk < 16; kk++) {
            float4 av0 = *(const float4*)&As[kk][ty * 4];
            float4 av1 = *(const float4*)&As[kk][ty * 4 + 64];
            float4 bv0 = *(const float4*)&Bs[kk][tx * 4];
            float4 bv1 = *(const float4*)&Bs[kk][tx * 4 + 64];
            float a[8] = {av0.x, av0.y, av0.z, av0.w, av1.x, av1.y, av1.z, av1.w};
            float b[8] = {bv0.x, bv0.y, bv0.z, bv0.w, bv1.x, bv1.y, bv1.z, bv1.w};
#pragma unroll
            for (int i = 0; i < 8; i++)
#pragma unroll
                for (int j = 0; j < 8; j++)
                    acc[i][j] = fmaf(a[i], b[j], acc[i][j]);
        }
        __syncthreads();
    }

    // ---- epilogue ----
#pragma unroll
    for (int i = 0; i < 8; i++) {
        int m = mtile + ty * 4 + (i < 4 ? i : 64 + i - 4);
#pragma unroll
        for (int j = 0; j < 8; j++) {
            int col = ntile + tx * 4 + (j < 4 ? j : 64 + j - 4);
            if (col >= Nb) continue;
            float v = acc[i][j];
            if (bias) v = fmaf(bscale, bias[col], v);
            acc[i][j] = v;
            if (CMODE == 0) {
                C[(size_t)m * ldc + col] = v;
            }
        }
        if (CMODE == 1) {
            int b = m >> 12, n = m & 4095;
#pragma unroll
            for (int jp = 0; jp < 4; jp++) {
                int j0 = jp * 2;
                int col = ntile + tx * 4 + (j0 < 4 ? j0 : 64 + j0 - 4);
                int h = col >> 5, c = col & 31;
                size_t idx = (((size_t)(b * 8 + h) * 4096 + n) << 5) + c;
                __half2 hv = __floats2half2_rn(acc[i][j0], acc[i][j0 + 1]);
                *(__half2*)&Ch[idx] = hv;
            }
        }
    }
}

// ---------------- sampling + softmax + attention-weighted sum --------------
__global__ void __launch_bounds__(256) sample_kernel(float* __restrict__ headout) {
    const int bn = blockIdx.x;
    const int h = threadIdx.x >> 5;
    const int lane = threadIdx.x & 31;
    const int b = bn >> 12;
    const int n = bn & 4095;

    const float* oa = g_offattn + (size_t)bn * NOA;

    float w[PP];
    float mx = -1e30f;
#pragma unroll
    for (int p = 0; p < PP; p++) {
        w[p] = oa[NOFF + h * PP + p];
        mx = fmaxf(mx, w[p]);
    }
    float s = 0.f;
#pragma unroll
    for (int p = 0; p < PP; p++) { w[p] = __expf(w[p] - mx); s += w[p]; }
    float inv = 1.f / s;
#pragma unroll
    for (int p = 0; p < PP; p++) w[p] *= inv;

    const float ref_xn = (float)(n & 63) * (2.0f / 63.0f) - 1.0f;
    const float ref_yn = (float)(n >> 6) * (2.0f / 63.0f) - 1.0f;

    const __half* img = g_vimg + ((size_t)(b * 8 + h)) * (4096u * 32u);

    float acc = 0.f;
#pragma unroll
    for (int p = 0; p < PP; p++) {
        float ox = oa[h * 18 + p * 2 + 0];
        float oy = oa[h * 18 + p * 2 + 1];
        float gx = (ref_xn + ox + 1.0f) * 0.5f * 63.0f;
        float gy = (ref_yn + oy + 1.0f) * 0.5f * 63.0f;
        float x0f = floorf(gx), y0f = floorf(gy);
        int x0 = (int)x0f, y0 = (int)y0f;
        float wx1 = gx - x0f, wy1 = gy - y0f;
        float wx0 = 1.f - wx1, wy0 = 1.f - wy1;

        bool vx0 = (x0 >= 0) & (x0 < 64);
        bool vx1 = (x0 >= -1) & (x0 < 63);
        bool vy0 = (y0 >= 0) & (y0 < 64);
        bool vy1 = (y0 >= -1) & (y0 < 63);

        float v00 = (vx0 && vy0) ? __half2float(img[((size_t)(y0 * 64 + x0) << 5) + lane]) : 0.f;
        float v10 = (vx1 && vy0) ? __half2float(img[((size_t)(y0 * 64 + x0 + 1) << 5) + lane]) : 0.f;
        float v01 = (vx0 && vy1) ? __half2float(img[((size_t)((y0 + 1) * 64 + x0) << 5) + lane]) : 0.f;
        float v11 = (vx1 && vy1) ? __half2float(img[((size_t)((y0 + 1) * 64 + x0 + 1) << 5) + lane]) : 0.f;

        float bil = wx0 * wy0 * v00 + wx1 * wy0 * v10 + wx0 * wy1 * v01 + wx1 * wy1 * v11;
        acc = fmaf(w[p], bil, acc);
    }
    headout[(size_t)bn * D_ + h * DH + lane] = acc;
}

// ---------------- launch ----------------------------------------------------
extern "C" void kernel_launch(void* const* d_in, const int* in_sizes, int n_in,
                              void* d_out, int out_size) {
    const float* x      = (const float*)d_in[0];
    const float* W_off  = (const float*)d_in[1];
    const float* b_off  = (const float*)d_in[2];
    const float* W_attn = (const float*)d_in[3];
    const float* b_attn = (const float*)d_in[4];
    const float* W_v    = (const float*)d_in[5];
    const float* b_v    = (const float*)d_in[6];
    const float* W_o    = (const float*)d_in[7];
    const float* b_o    = (const float*)d_in[8];
    float* out = (float*)d_out;

    float *p_woa, *p_boa, *p_offattn, *p_headout;
    __half* p_vimg;
    cudaGetSymbolAddress((void**)&p_woa,     g_woa);
    cudaGetSymbolAddress((void**)&p_boa,     g_boa);
    cudaGetSymbolAddress((void**)&p_offattn, g_offattn);
    cudaGetSymbolAddress((void**)&p_vimg,    g_vimg);
    cudaGetSymbolAddress((void**)&p_headout, g_headout);

    // 1. pack [W_off | W_attn] and biases
    pack_kernel<<<256, 256>>>(W_off, b_off, W_attn, b_attn);

    // 2. offsets+attn logits: query (= x[:,:,1,:], strided) @ packed W (Nb=216)
    gemm_k<0, 0><<<dim3(2, M_ / 128), 256>>>(x + 256, 768, p_woa, NOA,
                                             p_boa, 1.0f, p_offattn, NOA, nullptr);

    // 3. value images: (sum_t x) @ W_v + 3*b_v -> fp16 vimg scatter
    gemm_k<1, 1><<<dim3(2, M_ / 128), 256>>>(x, 768, W_v, D_,
                                             b_v, 3.0f, nullptr, 0, p_vimg);

    // 4. softmax + bilinear sampling + attention reduce
    sample_kernel<<<M_, 256>>>(p_headout);

    // 5. output projection: headout @ W_o + b_o
    gemm_k<0, 0><<<dim3(2, M_ / 128), 256>>>(p_headout, D_, W_o, D_,
                                             b_o, 1.0f, out, D_, nullptr);
}

// round 3
// speedup vs baseline: 1.8571x; 1.2487x over previous
#include <cuda_runtime.h>
#include <cuda_fp16.h>
#include <cstdint>

#define B_  4
#define N_  4096      // 64*64
#define D_  256
#define HH  8
#define PP  9
#define DH  32
#define M_  (B_*N_)   // 16384
#define NOFF 144
#define NATT 72
#define NOA  216      // 144 + 72

// ---------------- device scratch (static) ----------------------------------
__device__ float  g_woa[256 * NOA];          // packed [W_off | W_attn]
__device__ float  g_boa[NOA];                // packed [b_off | b_attn]
__device__ float  g_offattn[(size_t)M_ * NOA];
__device__ __half g_vimg[(size_t)M_ * D_];   // [(b*8+h)][n=y*64+x][c] fp16
__device__ float  g_headout[(size_t)M_ * D_];

// ---------------- pack W_off/W_attn into one 256x216 matrix ----------------
__global__ void __launch_bounds__(256) pack_kernel(
        const float* __restrict__ Woff, const float* __restrict__ boff,
        const float* __restrict__ Watt, const float* __restrict__ batt) {
    int k = blockIdx.x;          // 0..255
    int c = threadIdx.x;         // 0..255
    if (c < NOA) {
        float v = (c < NOFF) ? Woff[k * NOFF + c] : Watt[k * NATT + (c - NOFF)];
        g_woa[k * NOA + c] = v;
        if (k == 0) g_boa[c] = (c < NOFF) ? boff[c] : batt[c - NOFF];
    }
}

// ---------------- GEMM: C(Mx Nb) = A(Mx256) * B(256xNb) + bscale*bias ------
// BM=128, BN=128, BK=16, 256 threads, 8x8 microtile.
// AMODE 0: A row-major with leading dim lda
// AMODE 1: A row = sum of 3 temporal rows, lda=768
// CMODE 0: fp32 row-major ldc
// CMODE 1: fp16 scatter to vimg layout (((b*8+h)*4096+n)*32+c)
template<int AMODE, int CMODE>
__global__ void __launch_bounds__(256, 2) gemm_k(
        const float* __restrict__ A, int lda,
        const float* __restrict__ Bm, int Nb,
        const float* __restrict__ bias, float bscale,
        float* __restrict__ C, int ldc, __half* __restrict__ Ch)
{
    __shared__ float As[16][128];
    __shared__ float Bs[16][128];
    const int tid = threadIdx.x;
    const int mtile = blockIdx.y * 128;
    const int ntile = blockIdx.x * 128;
    const int tx = tid & 15;
    const int ty = tid >> 4;

    const int ar = tid >> 1;
    const int ak = (tid & 1) * 8;
    const int bk = tid >> 4;
    const int bn = (tid & 15) * 8;

    float acc[8][8];
#pragma unroll
    for (int i = 0; i < 8; i++)
#pragma unroll
        for (int j = 0; j < 8; j++) acc[i][j] = 0.f;

    const float* Arow = A + (size_t)(mtile + ar) * lda;

    for (int k0 = 0; k0 < 256; k0 += 16) {
        float4 a0, a1;
        const float* Ap = Arow + k0 + ak;
        if (AMODE == 0) {
            a0 = *(const float4*)Ap;
            a1 = *(const float4*)(Ap + 4);
        } else {
            float4 t0 = *(const float4*)(Ap);
            float4 t1 = *(const float4*)(Ap + 256);
            float4 t2 = *(const float4*)(Ap + 512);
            a0 = make_float4(t0.x + t1.x + t2.x, t0.y + t1.y + t2.y,
                             t0.z + t1.z + t2.z, t0.w + t1.w + t2.w);
            float4 u0 = *(const float4*)(Ap + 4);
            float4 u1 = *(const float4*)(Ap + 260);
            float4 u2 = *(const float4*)(Ap + 516);
            a1 = make_float4(u0.x + u1.x + u2.x, u0.y + u1.y + u2.y,
                             u0.z + u1.z + u2.z, u0.w + u1.w + u2.w);
        }
        As[ak + 0][ar] = a0.x; As[ak + 1][ar] = a0.y;
        As[ak + 2][ar] = a0.z; As[ak + 3][ar] = a0.w;
        As[ak + 4][ar] = a1.x; As[ak + 5][ar] = a1.y;
        As[ak + 6][ar] = a1.z; As[ak + 7][ar] = a1.w;

        {
            const float* Bp = Bm + (size_t)(k0 + bk) * Nb + ntile + bn;
            int gc = ntile + bn;
            float4 b0 = (gc + 4 <= Nb) ? *(const float4*)Bp
                                       : make_float4(0.f, 0.f, 0.f, 0.f);
            float4 b1 = (gc + 8 <= Nb) ? *(const float4*)(Bp + 4)
                                       : make_float4(0.f, 0.f, 0.f, 0.f);
            *(float4*)&Bs[bk][bn]     = b0;
            *(float4*)&Bs[bk][bn + 4] = b1;
        }
        __syncthreads();

#pragma unroll
        for (int kk = 0; kk < 16; kk++) {
            float4 av0 = *(const float4*)&As[kk][ty * 4];
            float4 av1 = *(const float4*)&As[kk][ty * 4 + 64];
            float4 bv0 = *(const float4*)&Bs[kk][tx * 4];
            float4 bv1 = *(const float4*)&Bs[kk][tx * 4 + 64];
            float a[8] = {av0.x, av0.y, av0.z, av0.w, av1.x, av1.y, av1.z, av1.w};
            float b[8] = {bv0.x, bv0.y, bv0.z, bv0.w, bv1.x, bv1.y, bv1.z, bv1.w};
#pragma unroll
            for (int i = 0; i < 8; i++)
#pragma unroll
                for (int j = 0; j < 8; j++)
                    acc[i][j] = fmaf(a[i], b[j], acc[i][j]);
        }
        __syncthreads();
    }

#pragma unroll
    for (int i = 0; i < 8; i++) {
        int m = mtile + ty * 4 + (i < 4 ? i : 64 + i - 4);
#pragma unroll
        for (int j = 0; j < 8; j++) {
            int col = ntile + tx * 4 + (j < 4 ? j : 64 + j - 4);
            if (col >= Nb) continue;
            float v = acc[i][j];
            if (bias) v = fmaf(bscale, bias[col], v);
            acc[i][j] = v;
            if (CMODE == 0) {
                C[(size_t)m * ldc + col] = v;
            }
        }
        if (CMODE == 1) {
            int b = m >> 12, n = m & 4095;
#pragma unroll
            for (int jp = 0; jp < 4; jp++) {
                int j0 = jp * 2;
                int col = ntile + tx * 4 + (j0 < 4 ? j0 : 64 + j0 - 4);
                int h = col >> 5, c = col & 31;
                size_t idx = (((size_t)(b * 8 + h) * 4096 + n) << 5) + c;
                __half2 hv = __floats2half2_rn(acc[i][j0], acc[i][j0 + 1]);
                *(__half2*)&Ch[idx] = hv;
            }
        }
    }
}

// ---------------- sampling: precompute (h,p) tables in smem, half2 lanes ---
// block = 128 threads = 4 warps; block per bn; warp = 2 heads; lane pair of ch
__global__ void __launch_bounds__(128) sample_kernel(float* __restrict__ headout) {
    __shared__ int4   s_idx[HH * PP];   // clamped corner indices (n' = y*64+x)
    __shared__ float4 s_wgt[HH * PP];   // bilinear weights * attn weight

    const int bn = blockIdx.x;
    const int b = bn >> 12;
    const int n = bn & 4095;
    const int t = threadIdx.x;

    // ---- precompute per (h, p): 72 threads ----
    if (t < HH * PP) {
        const int h = t / PP;
        const int p = t - h * PP;
        const float* oa = g_offattn + (size_t)bn * NOA;

        // softmax weight for (h, p)
        float mx = -1e30f;
#pragma unroll
        for (int q = 0; q < PP; q++) mx = fmaxf(mx, oa[NOFF + h * PP + q]);
        float s = 0.f;
#pragma unroll
        for (int q = 0; q < PP; q++) s += __expf(oa[NOFF + h * PP + q] - mx);
        const float wa = __expf(oa[NOFF + h * PP + p] - mx) / s;

        const float ref_xn = (float)(n & 63) * (2.0f / 63.0f) - 1.0f;
        const float ref_yn = (float)(n >> 6) * (2.0f / 63.0f) - 1.0f;
        float ox = oa[h * 18 + p * 2 + 0];
        float oy = oa[h * 18 + p * 2 + 1];
        float gx = (ref_xn + ox + 1.0f) * 0.5f * 63.0f;
        float gy = (ref_yn + oy + 1.0f) * 0.5f * 63.0f;
        float x0f = floorf(gx), y0f = floorf(gy);
        int x0 = (int)x0f, y0 = (int)y0f;
        float wx1 = gx - x0f, wy1 = gy - y0f;
        float wx0 = 1.f - wx1, wy0 = 1.f - wy1;

        float vx0 = (x0 >= 0 && x0 < 64) ? 1.f : 0.f;
        float vx1 = (x0 >= -1 && x0 < 63) ? 1.f : 0.f;
        float vy0 = (y0 >= 0 && y0 < 64) ? 1.f : 0.f;
        float vy1 = (y0 >= -1 && y0 < 63) ? 1.f : 0.f;

        int cx0 = min(max(x0, 0), 63);
        int cx1 = min(max(x0 + 1, 0), 63);
        int cy0 = min(max(y0, 0), 63) * 64;
        int cy1 = min(max(y0 + 1, 0), 63) * 64;

        s_idx[t] = make_int4(cy0 + cx0, cy0 + cx1, cy1 + cx0, cy1 + cx1);
        s_wgt[t] = make_float4(wa * wx0 * wy0 * vx0 * vy0,
                               wa * wx1 * wy0 * vx1 * vy0,
                               wa * wx0 * wy1 * vx0 * vy1,
                               wa * wx1 * wy1 * vx1 * vy1);
    }
    __syncthreads();

    // ---- main: warp covers 2 heads; 16 lanes per head; lane = 2 channels ----
    const int wid = t >> 5;
    const int lane = t & 31;
    const int half = lane >> 4;           // which head within warp
    const int sub = lane & 15;            // channel pair index
    const int h = wid * 2 + half;

    const __half2* img2 = (const __half2*)g_vimg
                        + ((size_t)(b * 8 + h) * 4096) * 16 + sub;

    float accx = 0.f, accy = 0.f;
#pragma unroll
    for (int p = 0; p < PP; p++) {
        int4   id = s_idx[h * PP + p];
        float4 w  = s_wgt[h * PP + p];
        float2 v00 = __half22float2(img2[id.x * 16]);
        float2 v10 = __half22float2(img2[id.y * 16]);
        float2 v01 = __half22float2(img2[id.z * 16]);
        float2 v11 = __half22float2(img2[id.w * 16]);
        accx = fmaf(w.x, v00.x, accx); accy = fmaf(w.x, v00.y, accy);
        accx = fmaf(w.y, v10.x, accx); accy = fmaf(w.y, v10.y, accy);
        accx = fmaf(w.z, v01.x, accx); accy = fmaf(w.z, v01.y, accy);
        accx = fmaf(w.w, v11.x, accx); accy = fmaf(w.w, v11.y, accy);
    }
    *(float2*)&headout[(size_t)bn * D_ + h * DH + sub * 2] = make_float2(accx, accy);
}

// ---------------- launch ----------------------------------------------------
extern "C" void kernel_launch(void* const* d_in, const int* in_sizes, int n_in,
                              void* d_out, int out_size) {
    const float* x      = (const float*)d_in[0];
    const float* W_off  = (const float*)d_in[1];
    const float* b_off  = (const float*)d_in[2];
    const float* W_attn = (const float*)d_in[3];
    const float* b_attn = (const float*)d_in[4];
    const float* W_v    = (const float*)d_in[5];
    const float* b_v    = (const float*)d_in[6];
    const float* W_o    = (const float*)d_in[7];
    const float* b_o    = (const float*)d_in[8];
    float* out = (float*)d_out;

    float *p_woa, *p_boa, *p_offattn, *p_headout;
    __half* p_vimg;
    cudaGetSymbolAddress((void**)&p_woa,     g_woa);
    cudaGetSymbolAddress((void**)&p_boa,     g_boa);
    cudaGetSymbolAddress((void**)&p_offattn, g_offattn);
    cudaGetSymbolAddress((void**)&p_vimg,    g_vimg);
    cudaGetSymbolAddress((void**)&p_headout, g_headout);

    // 1. pack [W_off | W_attn] and biases
    pack_kernel<<<256, 256>>>(W_off, b_off, W_attn, b_attn);

    // 2. offsets+attn logits: query (= x[:,:,1,:], strided) @ packed W (Nb=216)
    gemm_k<0, 0><<<dim3(2, M_ / 128), 256>>>(x + 256, 768, p_woa, NOA,
                                             p_boa, 1.0f, p_offattn, NOA, nullptr);

    // 3. value images: (sum_t x) @ W_v + 3*b_v -> fp16 vimg scatter
    gemm_k<1, 1><<<dim3(2, M_ / 128), 256>>>(x, 768, W_v, D_,
                                             b_v, 3.0f, nullptr, 0, p_vimg);

    // 4. softmax + bilinear sampling + attention reduce
    sample_kernel<<<M_, 128>>>(p_headout);

    // 5. output projection: headout @ W_o + b_o
    gemm_k<0, 0><<<dim3(2, M_ / 128), 256>>>(p_headout, D_, W_o, D_,
                                             b_o, 1.0f, out, D_, nullptr);
}

// round 5
// speedup vs baseline: 2.7244x; 1.4670x over previous
#include <cuda_runtime.h>
#include <cuda_fp16.h>
#include <cuda_bf16.h>
#include <cstdint>

#define B_  4
#define N_  4096
#define D_  256
#define HH  8
#define PP  9
#define DH  32
#define M_  (B_*N_)   // 16384
#define NOFF 144
#define NATT 72
#define NOA  216

// ---------------- device scratch (static) ----------------------------------
// B fragments: [kk(16)][j(32)][term(2)][lane(32)] as uint2 (b0,b1)
__device__ uint2  g_bfrag0[16 * 32 * 2 * 32];   // W_off|W_attn packed (cols >=216 zero)
__device__ uint2  g_bfrag1[16 * 32 * 2 * 32];   // W_v
__device__ uint2  g_bfrag2[16 * 32 * 2 * 32];   // W_o
__device__ float  g_boa[NOA];
__device__ float  g_offattn[(size_t)M_ * NOA];
__device__ __half g_vimg[(size_t)M_ * D_];      // [(b*8+h)][n=y*64+x][c]
__device__ float  g_headout[(size_t)M_ * D_];

// ---------------- helpers ----------------------------------------------------
__device__ __forceinline__ uint32_t bf2bits(float a, float b) {
    __nv_bfloat162 h = __floats2bfloat162_rn(a, b);
    return *reinterpret_cast<uint32_t*>(&h);
}
__device__ __forceinline__ void mma16816(float* c,
        uint32_t a0, uint32_t a1, uint32_t a2, uint32_t a3,
        uint32_t b0, uint32_t b1) {
    asm("mma.sync.aligned.m16n8k16.row.col.f32.bf16.bf16.f32 "
        "{%0,%1,%2,%3}, {%4,%5,%6,%7}, {%8,%9}, {%0,%1,%2,%3};"
        : "+f"(c[0]), "+f"(c[1]), "+f"(c[2]), "+f"(c[3])
        : "r"(a0), "r"(a1), "r"(a2), "r"(a3), "r"(b0), "r"(b1));
}

// ---------------- pack: B matrices -> mma fragment order + hi/lo split -------
// grid (128, 3), 256 threads. idx = kk*2048 + j*64 + term*32 + lane
__global__ void __launch_bounds__(256) pack_kernel(
        const float* __restrict__ Woff, const float* __restrict__ boff,
        const float* __restrict__ Watt, const float* __restrict__ batt,
        const float* __restrict__ Wv,   const float* __restrict__ Wo) {
    int idx = blockIdx.x * 256 + threadIdx.x;    // 0..32767
    int mat = blockIdx.y;
    int lane = idx & 31;
    int term = (idx >> 5) & 1;
    int j    = (idx >> 6) & 31;
    int kk   = idx >> 11;
    int gid = lane >> 2, tig = lane & 3;
    int n = j * 8 + gid;
    int k0 = kk * 16 + tig * 2;

    float v[4];
#pragma unroll
    for (int q = 0; q < 4; q++) {
        int k = k0 + (q & 1) + (q >> 1) * 8;
        float w = 0.f;
        if (mat == 0) {
            if (n < NOFF)      w = Woff[k * NOFF + n];
            else if (n < NOA)  w = Watt[k * NATT + (n - NOFF)];
        } else if (mat == 1) {
            w = Wv[k * 256 + n];
        } else {
            w = Wo[k * 256 + n];
        }
        v[q] = w;
    }
    if (term == 1) {
#pragma unroll
        for (int q = 0; q < 4; q++) {
            float hi = __bfloat162float(__float2bfloat16(v[q]));
            v[q] = v[q] - hi;
        }
    }
    uint2 r = make_uint2(bf2bits(v[0], v[1]), bf2bits(v[2], v[3]));
    if (mat == 0)      g_bfrag0[idx] = r;
    else if (mat == 1) g_bfrag1[idx] = r;
    else               g_bfrag2[idx] = r;

    if (mat == 0 && idx < NOA)
        g_boa[idx] = (idx < NOFF) ? boff[idx] : batt[idx - NOFF];
}

// ---------------- bf16x3 mma.sync GEMM ---------------------------------------
// C(128x128 tile) = A(128x256) @ W(256x*) + bscale*bias
// AMODE 0: A rows (lda); AMODE 1: row = sum of 3 temporal rows (lda=768)
// CMODE 0: fp32 row-major [ldc], cols < NCOUT; CMODE 1: fp16 vimg scatter
#define APITCH 152   // bytes per A-smem row (16 kpairs * 8B + 24 pad)
template<int AMODE, int CMODE, int NCOUT>
__global__ void __launch_bounds__(256) gemm_mma(
        const float* __restrict__ A, int lda,
        const uint2* __restrict__ Bfrag,
        const float* __restrict__ bias, float bscale,
        float* __restrict__ C, int ldc)
{
    __shared__ char smem[128 * APITCH];
    const int tid = threadIdx.x;
    const int wid = tid >> 5, lane = tid & 31;
    const int warp_m = wid & 1, warp_n = wid >> 1;
    const int mtile = blockIdx.y * 128;
    const int nbase = blockIdx.x * 128 + warp_n * 32;
    const int gid = lane >> 2, tig = lane & 3;

    float acc[4][4][4];
#pragma unroll
    for (int mt = 0; mt < 4; mt++)
#pragma unroll
        for (int j = 0; j < 4; j++)
#pragma unroll
            for (int q = 0; q < 4; q++) acc[mt][j][q] = 0.f;

    // A loader: thread -> (row = tid/2, half = (tid&1)*16 k-elems)
    const int arow = tid >> 1;
    const int ahalf = (tid & 1) * 16;
    const float* Abase = A + (size_t)(mtile + arow) * lda + ahalf;
    char* arowp = smem + arow * APITCH + (ahalf >> 1) * 8;

    // B prefetch (depth 2): ptr(kk, j, term) = ((kk*32 + jg)*2 + term)*32 + lane
    const int jg = blockIdx.x * 16 + warp_n * 4;
    const uint2* Bp = Bfrag + (size_t)jg * 64 + lane;   // + kk*2048 + j*64 + term*32
    uint2 bbuf[2][4][2];
#pragma unroll
    for (int j = 0; j < 4; j++)
#pragma unroll
        for (int t = 0; t < 2; t++) {
            bbuf[0][j][t] = __ldg(Bp + j * 64 + t * 32);
            bbuf[1][j][t] = __ldg(Bp + 2048 + j * 64 + t * 32);
        }

    for (int kk = 0; kk < 16; kk++) {
        if ((kk & 1) == 0) {
            // ---- stage A chunk (32 k-elems) ----
            __syncthreads();
            const float* Ap = Abase + (kk >> 1) * 32;
            float v[16];
#pragma unroll
            for (int q = 0; q < 4; q++) {
                float4 t0 = *(const float4*)(Ap + q * 4);
                if (AMODE == 1) {
                    float4 t1 = *(const float4*)(Ap + q * 4 + 256);
                    float4 t2 = *(const float4*)(Ap + q * 4 + 512);
                    t0.x += t1.x + t2.x; t0.y += t1.y + t2.y;
                    t0.z += t1.z + t2.z; t0.w += t1.w + t2.w;
                }
                v[q * 4 + 0] = t0.x; v[q * 4 + 1] = t0.y;
                v[q * 4 + 2] = t0.z; v[q * 4 + 3] = t0.w;
            }
#pragma unroll
            for (int e = 0; e < 8; e++) {
                float v0 = v[2 * e], v1 = v[2 * e + 1];
                __nv_bfloat16 h0 = __float2bfloat16(v0);
                __nv_bfloat16 h1 = __float2bfloat16(v1);
                float l0 = v0 - __bfloat162float(h0);
                float l1 = v1 - __bfloat162float(h1);
                __nv_bfloat162 hp = __halves2bfloat162(h0, h1);
                uint2 st = make_uint2(*reinterpret_cast<uint32_t*>(&hp),
                                      bf2bits(l0, l1));
                *(uint2*)(arowp + e * 8) = st;
            }
            __syncthreads();
        }
        const int kk2 = kk & 1;
        const int buf = kk & 1;

        // ---- A fragments + MMA ----
#pragma unroll
        for (int mt = 0; mt < 4; mt++) {
            const char* ab = smem + (warp_m * 64 + mt * 16 + gid) * APITCH
                           + (kk2 * 8 + tig) * 8;
            uint2 u0 = *(const uint2*)(ab);
            uint2 u1 = *(const uint2*)(ab + 8 * APITCH);
            uint2 u2 = *(const uint2*)(ab + 32);
            uint2 u3 = *(const uint2*)(ab + 8 * APITCH + 32);
#pragma unroll
            for (int j = 0; j < 4; j++) {
                uint2 bh = bbuf[buf][j][0];
                uint2 bl = bbuf[buf][j][1];
                mma16816(acc[mt][j], u0.x, u1.x, u2.x, u3.x, bh.x, bh.y);
                mma16816(acc[mt][j], u0.y, u1.y, u2.y, u3.y, bh.x, bh.y);
                mma16816(acc[mt][j], u0.x, u1.x, u2.x, u3.x, bl.x, bl.y);
            }
        }
        // ---- prefetch B for kk+2 into the buffer just consumed ----
        if (kk < 14) {
            const uint2* Bn = Bp + (size_t)(kk + 2) * 2048;
#pragma unroll
            for (int j = 0; j < 4; j++)
#pragma unroll
                for (int t = 0; t < 2; t++)
                    bbuf[buf][j][t] = __ldg(Bn + j * 64 + t * 32);
        }
    }

    // ---- epilogue: direct store from accumulators ----
#pragma unroll
    for (int mt = 0; mt < 4; mt++) {
        int row0 = mtile + warp_m * 64 + mt * 16 + gid;
#pragma unroll
        for (int j = 0; j < 4; j++) {
            int col = nbase + j * 8 + tig * 2;
            if (col >= NCOUT) continue;
            float b0 = fmaf(bscale, bias[col], acc[mt][j][0]);
            float b1 = fmaf(bscale, bias[col + 1], acc[mt][j][1]);
            float b2 = fmaf(bscale, bias[col], acc[mt][j][2]);
            float b3 = fmaf(bscale, bias[col + 1], acc[mt][j][3]);
            if (CMODE == 0) {
                *(float2*)&C[(size_t)row0 * ldc + col] = make_float2(b0, b1);
                *(float2*)&C[(size_t)(row0 + 8) * ldc + col] = make_float2(b2, b3);
            } else {
                int h = col >> 5, cc = col & 31;
                int gm0 = row0, gm1 = row0 + 8;
                int bb0 = gm0 >> 12, nn0 = gm0 & 4095;
                int bb1 = gm1 >> 12, nn1 = gm1 & 4095;
                *(__half2*)&g_vimg[(((size_t)(bb0 * 8 + h) * 4096 + nn0) << 5) + cc] =
                    __floats2half2_rn(b0, b1);
                *(__half2*)&g_vimg[(((size_t)(bb1 * 8 + h) * 4096 + nn1) << 5) + cc] =
                    __floats2half2_rn(b2, b3);
            }
        }
    }
}

// ---------------- sampling (unchanged) ----------------------------------------
__global__ void __launch_bounds__(128) sample_kernel(float* __restrict__ headout) {
    __shared__ int4   s_idx[HH * PP];
    __shared__ float4 s_wgt[HH * PP];

    const int bn = blockIdx.x;
    const int b = bn >> 12;
    const int n = bn & 4095;
    const int t = threadIdx.x;

    if (t < HH * PP) {
        const int h = t / PP;
        const int p = t - h * PP;
        const float* oa = g_offattn + (size_t)bn * NOA;

        float mx = -1e30f;
#pragma unroll
        for (int q = 0; q < PP; q++) mx = fmaxf(mx, oa[NOFF + h * PP + q]);
        float s = 0.f;
#pragma unroll
        for (int q = 0; q < PP; q++) s += __expf(oa[NOFF + h * PP + q] - mx);
        const float wa = __expf(oa[NOFF + h * PP + p] - mx) / s;

        const float ref_xn = (float)(n & 63) * (2.0f / 63.0f) - 1.0f;
        const float ref_yn = (float)(n >> 6) * (2.0f / 63.0f) - 1.0f;
        float ox = oa[h * 18 + p * 2 + 0];
        float oy = oa[h * 18 + p * 2 + 1];
        float gx = (ref_xn + ox + 1.0f) * 0.5f * 63.0f;
        float gy = (ref_yn + oy + 1.0f) * 0.5f * 63.0f;
        float x0f = floorf(gx), y0f = floorf(gy);
        int x0 = (int)x0f, y0 = (int)y0f;
        float wx1 = gx - x0f, wy1 = gy - y0f;
        float wx0 = 1.f - wx1, wy0 = 1.f - wy1;

        float vx0 = (x0 >= 0 && x0 < 64) ? 1.f : 0.f;
        float vx1 = (x0 >= -1 && x0 < 63) ? 1.f : 0.f;
        float vy0 = (y0 >= 0 && y0 < 64) ? 1.f : 0.f;
        float vy1 = (y0 >= -1 && y0 < 63) ? 1.f : 0.f;

        int cx0 = min(max(x0, 0), 63);
        int cx1 = min(max(x0 + 1, 0), 63);
        int cy0 = min(max(y0, 0), 63) * 64;
        int cy1 = min(max(y0 + 1, 0), 63) * 64;

        s_idx[t] = make_int4(cy0 + cx0, cy0 + cx1, cy1 + cx0, cy1 + cx1);
        s_wgt[t] = make_float4(wa * wx0 * wy0 * vx0 * vy0,
                               wa * wx1 * wy0 * vx1 * vy0,
                               wa * wx0 * wy1 * vx0 * vy1,
                               wa * wx1 * wy1 * vx1 * vy1);
    }
    __syncthreads();

    const int wid = t >> 5;
    const int lane = t & 31;
    const int half = lane >> 4;
    const int sub = lane & 15;
    const int h = wid * 2 + half;

    const __half2* img2 = (const __half2*)g_vimg
                        + ((size_t)(b * 8 + h) * 4096) * 16 + sub;

    float accx = 0.f, accy = 0.f;
#pragma unroll
    for (int p = 0; p < PP; p++) {
        int4   id = s_idx[h * PP + p];
        float4 w  = s_wgt[h * PP + p];
        float2 v00 = __half22float2(img2[id.x * 16]);
        float2 v10 = __half22float2(img2[id.y * 16]);
        float2 v01 = __half22float2(img2[id.z * 16]);
        float2 v11 = __half22float2(img2[id.w * 16]);
        accx = fmaf(w.x, v00.x, accx); accy = fmaf(w.x, v00.y, accy);
        accx = fmaf(w.y, v10.x, accx); accy = fmaf(w.y, v10.y, accy);
        accx = fmaf(w.z, v01.x, accx); accy = fmaf(w.z, v01.y, accy);
        accx = fmaf(w.w, v11.x, accx); accy = fmaf(w.w, v11.y, accy);
    }
    *(float2*)&headout[(size_t)bn * D_ + h * DH + sub * 2] = make_float2(accx, accy);
}

// ---------------- launch --------------------------------------------------------
extern "C" void kernel_launch(void* const* d_in, const int* in_sizes, int n_in,
                              void* d_out, int out_size) {
    const float* x      = (const float*)d_in[0];
    const float* W_off  = (const float*)d_in[1];
    const float* b_off  = (const float*)d_in[2];
    const float* W_attn = (const float*)d_in[3];
    const float* b_attn = (const float*)d_in[4];
    const float* W_v    = (const float*)d_in[5];
    const float* b_v    = (const float*)d_in[6];
    const float* W_o    = (const float*)d_in[7];
    const float* b_o    = (const float*)d_in[8];
    float* out = (float*)d_out;

    uint2 *p_bf0, *p_bf1, *p_bf2;
    float *p_boa, *p_offattn, *p_headout;
    cudaGetSymbolAddress((void**)&p_bf0,     g_bfrag0);
    cudaGetSymbolAddress((void**)&p_bf1,     g_bfrag1);
    cudaGetSymbolAddress((void**)&p_bf2,     g_bfrag2);
    cudaGetSymbolAddress((void**)&p_boa,     g_boa);
    cudaGetSymbolAddress((void**)&p_offattn, g_offattn);
    cudaGetSymbolAddress((void**)&p_headout, g_headout);

    // 1. pack weights into mma fragment order (hi/lo bf16 split)
    pack_kernel<<<dim3(128, 3), 256>>>(W_off, b_off, W_attn, b_attn, W_v, W_o);

    // 2. offsets + attn logits: query @ [W_off|W_attn]
    gemm_mma<0, 0, NOA><<<dim3(2, 128), 256>>>(
        x + 256, 768, p_bf0, p_boa, 1.0f, p_offattn, NOA);

    // 3. value images: (sum_t x) @ W_v + 3*b_v -> fp16 vimg
    gemm_mma<1, 1, 256><<<dim3(2, 128), 256>>>(
        x, 768, p_bf1, b_v, 3.0f, nullptr, 0);

    // 4. softmax + bilinear sampling + attention reduce
    sample_kernel<<<M_, 128>>>(p_headout);

    // 5. output projection: headout @ W_o + b_o
    gemm_mma<0, 0, 256><<<dim3(2, 128), 256>>>(
        p_headout, 256, p_bf2, b_o, 1.0f, out, 256);
}